// round 14
// baseline (speedup 1.0000x reference)
#include <cuda_runtime.h>
#include <cuda_bf16.h>
#include <cuda_fp8.h>
#include <cstdint>

#define M_DIM 8192
#define N_DIM 2048
#define K_DIM 2048
#define KCH 16     // K / 128
#define NBLK 16    // N / 128

// ---------------- scratch (allocation-free: __device__ globals) ----------------
__device__ __align__(16) uint8_t g_xq[(size_t)M_DIM * K_DIM];  // 16 MB
__device__ __align__(16) uint8_t g_wq[(size_t)N_DIM * K_DIM];  //  4 MB
__device__ float g_sx[M_DIM * KCH];
__device__ float g_sw[NBLK * KCH];

// pack 4 floats -> 4 e4m3 bytes (RN, satfinite)
__device__ __forceinline__ uint32_t fp8x4(float a, float b, float c, float d, float r) {
    __nv_fp8x2_storage_t q01 =
        __nv_cvt_float2_to_fp8x2(make_float2(a * r, b * r), __NV_SATFINITE, __NV_E4M3);
    __nv_fp8x2_storage_t q23 =
        __nv_cvt_float2_to_fp8x2(make_float2(c * r, d * r), __NV_SATFINITE, __NV_E4M3);
    return (uint32_t)q01 | ((uint32_t)q23 << 16);
}

// ---------------- fused quant: blocks [0,16384) -> x, [16384,16640) -> w ----------------
__global__ void quant_fused(const float* __restrict__ x, const float* __restrict__ w) {
    if (blockIdx.x < 16384) {
        // ---- x: per (row, 128-chunk) scale; warp per chunk ----
        int wid = threadIdx.x >> 5, lane = threadIdx.x & 31;
        int id = blockIdx.x * 8 + wid;
        int row = id >> 4, c = id & 15;
        const float4* src = reinterpret_cast<const float4*>(x + (size_t)row * K_DIM + c * 128);
        float4 v = src[lane];
        float amax = fmaxf(fmaxf(fabsf(v.x), fabsf(v.y)), fmaxf(fabsf(v.z), fabsf(v.w)));
        #pragma unroll
        for (int o = 16; o > 0; o >>= 1)
            amax = fmaxf(amax, __shfl_xor_sync(0xffffffffu, amax, o));
        amax = fmaxf(amax, 1e-4f);
        float r = 448.0f / amax;
        *reinterpret_cast<uint32_t*>(g_xq + (size_t)row * K_DIM + c * 128 + lane * 4) =
            fp8x4(v.x, v.y, v.z, v.w, r);
        if (lane == 0) g_sx[id] = amax / 448.0f;
    } else {
        // ---- w: per 128x128 block scale; CTA per block ----
        __shared__ float red[8];
        int b = blockIdx.x - 16384;
        int nb = b >> 4, kc = b & 15;
        int t = threadIdx.x;
        int lane = t & 31, wid = t >> 5;
        int rowInBlk = t >> 1;
        int colOff = (t & 1) * 64;
        const float4* base = reinterpret_cast<const float4*>(
            w + (size_t)(nb * 128 + rowInBlk) * K_DIM + kc * 128 + colOff);
        float4 v[16];
        float amax = 0.0f;
        #pragma unroll
        for (int i = 0; i < 16; i++) {
            v[i] = base[i];
            amax = fmaxf(amax, fmaxf(fmaxf(fabsf(v[i].x), fabsf(v[i].y)),
                                     fmaxf(fabsf(v[i].z), fabsf(v[i].w))));
        }
        #pragma unroll
        for (int o = 16; o > 0; o >>= 1)
            amax = fmaxf(amax, __shfl_xor_sync(0xffffffffu, amax, o));
        if (lane == 0) red[wid] = amax;
        __syncthreads();
        if (t == 0) {
            float m = red[0];
            #pragma unroll
            for (int i = 1; i < 8; i++) m = fmaxf(m, red[i]);
            red[0] = fmaxf(m, 1e-4f);
        }
        __syncthreads();
        float s = red[0];
        float r = 448.0f / s;
        uint8_t* dst = g_wq + (size_t)(nb * 128 + rowInBlk) * K_DIM + kc * 128 + colOff;
        #pragma unroll
        for (int i = 0; i < 16; i++)
            *reinterpret_cast<uint32_t*>(dst + i * 4) =
                fp8x4(v[i].x, v[i].y, v[i].z, v[i].w, r);
        if (t == 0) g_sw[nb * KCH + kc] = s / 448.0f;
    }
}

// ------- GEMM: fp8 QMMA (m16n8k32), BK=128 (one chunk/stage), exact fp32 promotion -------
#define BM 128
#define BN 128
#define BK 128                    // fp8 elements per k-tile = one scale chunk
#define ARS 144                   // smem row stride bytes (128B data + 16 pad)
#define ABYTES (BM * ARS)         // 18432
#define BBYTES (BN * ARS)         // 18432
#define STAGE_BYTES (ABYTES + BBYTES)   // 36864
#define NSTAGE 3

__device__ __forceinline__ void cp_async16(uint32_t s, const void* g) {
    asm volatile("cp.async.cg.shared.global [%0], [%1], 16;\n" :: "r"(s), "l"(g));
}
__device__ __forceinline__ void ldsm4(uint32_t& r0, uint32_t& r1, uint32_t& r2, uint32_t& r3,
                                      uint32_t addr) {
    asm volatile("ldmatrix.sync.aligned.m8n8.x4.shared.b16 {%0,%1,%2,%3}, [%4];\n"
                 : "=r"(r0), "=r"(r1), "=r"(r2), "=r"(r3) : "r"(addr));
}
__device__ __forceinline__ void qmma(float* c, uint32_t a0, uint32_t a1, uint32_t a2,
                                     uint32_t a3, uint32_t b0, uint32_t b1) {
    asm volatile(
        "mma.sync.aligned.m16n8k32.row.col.f32.e4m3.e4m3.f32 "
        "{%0,%1,%2,%3}, {%4,%5,%6,%7}, {%8,%9}, {%0,%1,%2,%3};\n"
        : "+f"(c[0]), "+f"(c[1]), "+f"(c[2]), "+f"(c[3])
        : "r"(a0), "r"(a1), "r"(a2), "r"(a3), "r"(b0), "r"(b1));
}
__device__ __forceinline__ float bf16_round(float v) {
    return __bfloat162float(__float2bfloat16(v));
}

__global__ __launch_bounds__(256, 1) void gemm_kernel(float* __restrict__ out) {
    extern __shared__ __align__(16) unsigned char smem[];
    const int t = threadIdx.x;
    const int lane = t & 31, wid = t >> 5;
    const int gid = lane >> 2;            // groupID (0..7)
    const int tig = lane & 3;             // thread-in-group (0..3)
    const int warpM = wid >> 1, warpN = wid & 1;   // 4 x 2 warp grid, 32x64 warp tiles
    const int bm = blockIdx.y * BM, bn = blockIdx.x * BN;
    const int nb = bn >> 7;
    const uint32_t sbase = (uint32_t)__cvta_generic_to_shared(smem);

    float accO[2][8][4];
    float accI[2][8][4];
    #pragma unroll
    for (int i = 0; i < 2; i++)
        #pragma unroll
        for (int j = 0; j < 8; j++)
            #pragma unroll
            for (int k = 0; k < 4; k++) { accO[i][j][k] = 0.0f; accI[i][j][k] = 0.0f; }

    auto load_stage = [&](int kt, int stage) {
        uint32_t sA = sbase + stage * STAGE_BYTES;
        uint32_t sB = sA + ABYTES;
        int k0 = kt * BK;
        #pragma unroll
        for (int i = 0; i < 4; i++) {
            int idx = t + i * 256;
            int row = idx >> 3, ci = idx & 7;
            cp_async16(sA + row * ARS + ci * 16,
                       g_xq + (size_t)(bm + row) * K_DIM + k0 + ci * 16);
            cp_async16(sB + row * ARS + ci * 16,
                       g_wq + (size_t)(bn + row) * K_DIM + k0 + ci * 16);
        }
    };

    const int NKT = K_DIM / BK;  // 16
    load_stage(0, 0);
    asm volatile("cp.async.commit_group;\n");
    load_stage(1, 1);
    asm volatile("cp.async.commit_group;\n");

    for (int kt = 0; kt < NKT; kt++) {
        int stage = kt % NSTAGE;
        asm volatile("cp.async.wait_group 1;\n");
        __syncthreads();
        if (kt + 2 < NKT) {
            load_stage(kt + 2, (kt + 2) % NSTAGE);
            asm volatile("cp.async.commit_group;\n");
        }
        uint32_t sA = sbase + stage * STAGE_BYTES;
        uint32_t sB = sA + ABYTES;
        #pragma unroll
        for (int s = 0; s < 4; s++) {        // four k32 steps per 128B tile
            uint32_t a[2][4];
            #pragma unroll
            for (int ma = 0; ma < 2; ma++) {
                int row = warpM * 32 + ma * 16 + (lane & 15);
                uint32_t addr = sA + row * ARS + (2 * s + (lane >> 4)) * 16;
                ldsm4(a[ma][0], a[ma][1], a[ma][2], a[ma][3], addr);
            }
            uint32_t b[4][4];
            #pragma unroll
            for (int g = 0; g < 4; g++) {
                int nrow = warpN * 64 + g * 16 + (((lane >> 4) & 1) << 3) + (lane & 7);
                int cch = 2 * s + ((lane >> 3) & 1);
                uint32_t addr = sB + nrow * ARS + cch * 16;
                ldsm4(b[g][0], b[g][1], b[g][2], b[g][3], addr);
            }
            #pragma unroll
            for (int ma = 0; ma < 2; ma++)
                #pragma unroll
                for (int na = 0; na < 8; na++)
                    qmma(accI[ma][na], a[ma][0], a[ma][1], a[ma][2], a[ma][3],
                         b[na >> 1][(na & 1) * 2 + 0], b[na >> 1][(na & 1) * 2 + 1]);
        }
        // end of chunk kt: fold scales exactly
        {
            float swc = g_sw[nb * KCH + kt];
            #pragma unroll
            for (int ma = 0; ma < 2; ma++) {
                int row0 = bm + warpM * 32 + ma * 16 + gid;
                float s0 = g_sx[row0 * KCH + kt] * swc;
                float s1 = g_sx[(row0 + 8) * KCH + kt] * swc;
                #pragma unroll
                for (int na = 0; na < 8; na++) {
                    accO[ma][na][0] += s0 * accI[ma][na][0];
                    accO[ma][na][1] += s0 * accI[ma][na][1];
                    accO[ma][na][2] += s1 * accI[ma][na][2];
                    accO[ma][na][3] += s1 * accI[ma][na][3];
                    accI[ma][na][0] = 0.0f; accI[ma][na][1] = 0.0f;
                    accI[ma][na][2] = 0.0f; accI[ma][na][3] = 0.0f;
                }
            }
        }
    }

    // epilogue: bf16-rounded values stored as FP32 (output buffer is float32)
    #pragma unroll
    for (int ma = 0; ma < 2; ma++) {
        int row0 = bm + warpM * 32 + ma * 16 + gid;
        #pragma unroll
        for (int na = 0; na < 8; na++) {
            int col = bn + warpN * 64 + na * 8 + tig * 2;
            float2 v0, v1;
            v0.x = bf16_round(accO[ma][na][0]);
            v0.y = bf16_round(accO[ma][na][1]);
            v1.x = bf16_round(accO[ma][na][2]);
            v1.y = bf16_round(accO[ma][na][3]);
            *reinterpret_cast<float2*>(out + (size_t)row0 * N_DIM + col) = v0;
            *reinterpret_cast<float2*>(out + (size_t)(row0 + 8) * N_DIM + col) = v1;
        }
    }
}

extern "C" void kernel_launch(void* const* d_in, const int* in_sizes, int n_in,
                              void* d_out, int out_size) {
    const float* x = (const float*)d_in[0];
    const float* w = (const float*)d_in[1];
    if (n_in >= 2 && in_sizes[0] == N_DIM * K_DIM && in_sizes[1] > in_sizes[0]) {
        x = (const float*)d_in[1];
        w = (const float*)d_in[0];
    }
    float* out = (float*)d_out;
    (void)out_size;

    static bool attr_set = false;
    if (!attr_set) {
        cudaFuncSetAttribute(gemm_kernel, cudaFuncAttributeMaxDynamicSharedMemorySize,
                             NSTAGE * STAGE_BYTES);
        attr_set = true;
    }

    quant_fused<<<16384 + 256, 256>>>(x, w);
    gemm_kernel<<<dim3(N_DIM / BN, M_DIM / BM), 256, NSTAGE * STAGE_BYTES>>>(out);
}

// round 15
// speedup vs baseline: 1.1071x; 1.1071x over previous
#include <cuda_runtime.h>
#include <cuda_bf16.h>
#include <cuda_fp8.h>
#include <cstdint>

#define M_DIM 8192
#define N_DIM 2048
#define K_DIM 2048
#define KCH 16     // K / 128
#define NBLK 16    // N / 128

// ---------------- scratch (allocation-free: __device__ globals) ----------------
__device__ __align__(16) uint8_t g_xq[(size_t)M_DIM * K_DIM];  // 16 MB
__device__ __align__(16) uint8_t g_wq[(size_t)N_DIM * K_DIM];  //  4 MB
__device__ float g_sx[M_DIM * KCH];
__device__ float g_sw[NBLK * KCH];

// pack 4 floats -> 4 e4m3 bytes (RN, satfinite)
__device__ __forceinline__ uint32_t fp8x4(float a, float b, float c, float d, float r) {
    __nv_fp8x2_storage_t q01 =
        __nv_cvt_float2_to_fp8x2(make_float2(a * r, b * r), __NV_SATFINITE, __NV_E4M3);
    __nv_fp8x2_storage_t q23 =
        __nv_cvt_float2_to_fp8x2(make_float2(c * r, d * r), __NV_SATFINITE, __NV_E4M3);
    return (uint32_t)q01 | ((uint32_t)q23 << 16);
}

// ---------------- quantize x: per (row, 128-chunk) scale (unfused) ----------------
__global__ void quant_x_kernel(const float* __restrict__ x) {
    int wid = threadIdx.x >> 5, lane = threadIdx.x & 31;
    int id = blockIdx.x * 8 + wid;
    int row = id >> 4, c = id & 15;
    const float4* src = reinterpret_cast<const float4*>(x + (size_t)row * K_DIM + c * 128);
    float4 v = src[lane];
    float amax = fmaxf(fmaxf(fabsf(v.x), fabsf(v.y)), fmaxf(fabsf(v.z), fabsf(v.w)));
    #pragma unroll
    for (int o = 16; o > 0; o >>= 1) amax = fmaxf(amax, __shfl_xor_sync(0xffffffffu, amax, o));
    amax = fmaxf(amax, 1e-4f);
    float r = 448.0f / amax;
    *reinterpret_cast<uint32_t*>(g_xq + (size_t)row * K_DIM + c * 128 + lane * 4) =
        fp8x4(v.x, v.y, v.z, v.w, r);
    if (lane == 0) g_sx[id] = amax / 448.0f;
}

// ---------------- quantize w: per 128x128 block scale (unfused) ----------------
__global__ void quant_w_kernel(const float* __restrict__ w) {
    __shared__ float red[8];
    int nb = blockIdx.y, kc = blockIdx.x;
    int t = threadIdx.x;
    int lane = t & 31, wid = t >> 5;
    int rowInBlk = t >> 1;
    int colOff = (t & 1) * 64;
    const float4* base = reinterpret_cast<const float4*>(
        w + (size_t)(nb * 128 + rowInBlk) * K_DIM + kc * 128 + colOff);
    float4 v[16];
    float amax = 0.0f;
    #pragma unroll
    for (int i = 0; i < 16; i++) {
        v[i] = base[i];
        amax = fmaxf(amax, fmaxf(fmaxf(fabsf(v[i].x), fabsf(v[i].y)),
                                 fmaxf(fabsf(v[i].z), fabsf(v[i].w))));
    }
    #pragma unroll
    for (int o = 16; o > 0; o >>= 1) amax = fmaxf(amax, __shfl_xor_sync(0xffffffffu, amax, o));
    if (lane == 0) red[wid] = amax;
    __syncthreads();
    if (t == 0) {
        float m = red[0];
        #pragma unroll
        for (int i = 1; i < 8; i++) m = fmaxf(m, red[i]);
        red[0] = fmaxf(m, 1e-4f);
    }
    __syncthreads();
    float s = red[0];
    float r = 448.0f / s;
    uint8_t* dst = g_wq + (size_t)(nb * 128 + rowInBlk) * K_DIM + kc * 128 + colOff;
    #pragma unroll
    for (int i = 0; i < 16; i++)
        *reinterpret_cast<uint32_t*>(dst + i * 4) = fp8x4(v[i].x, v[i].y, v[i].z, v[i].w, r);
    if (t == 0) g_sw[nb * KCH + kc] = s / 448.0f;
}

// ---- GEMM: fp8 QMMA, BK=128, 512 threads / 16 warps (32x32 warp tiles), exact promotion ----
#define BM 128
#define BN 128
#define BK 128                    // fp8 elements per k-tile = one scale chunk
#define ARS 144                   // smem row stride bytes (128B data + 16 pad)
#define ABYTES (BM * ARS)         // 18432
#define BBYTES (BN * ARS)         // 18432
#define STAGE_BYTES (ABYTES + BBYTES)   // 36864
#define NSTAGE 3
#define NTHREADS 512

__device__ __forceinline__ void cp_async16(uint32_t s, const void* g) {
    asm volatile("cp.async.cg.shared.global [%0], [%1], 16;\n" :: "r"(s), "l"(g));
}
__device__ __forceinline__ void ldsm4(uint32_t& r0, uint32_t& r1, uint32_t& r2, uint32_t& r3,
                                      uint32_t addr) {
    asm volatile("ldmatrix.sync.aligned.m8n8.x4.shared.b16 {%0,%1,%2,%3}, [%4];\n"
                 : "=r"(r0), "=r"(r1), "=r"(r2), "=r"(r3) : "r"(addr));
}
__device__ __forceinline__ void qmma(float* c, uint32_t a0, uint32_t a1, uint32_t a2,
                                     uint32_t a3, uint32_t b0, uint32_t b1) {
    asm volatile(
        "mma.sync.aligned.m16n8k32.row.col.f32.e4m3.e4m3.f32 "
        "{%0,%1,%2,%3}, {%4,%5,%6,%7}, {%8,%9}, {%0,%1,%2,%3};\n"
        : "+f"(c[0]), "+f"(c[1]), "+f"(c[2]), "+f"(c[3])
        : "r"(a0), "r"(a1), "r"(a2), "r"(a3), "r"(b0), "r"(b1));
}
__device__ __forceinline__ float bf16_round(float v) {
    return __bfloat162float(__float2bfloat16(v));
}

__global__ __launch_bounds__(NTHREADS, 1) void gemm_kernel(float* __restrict__ out) {
    extern __shared__ __align__(16) unsigned char smem[];
    const int t = threadIdx.x;
    const int lane = t & 31, wid = t >> 5;
    const int gid = lane >> 2;            // groupID (0..7)
    const int tig = lane & 3;             // thread-in-group (0..3)
    const int warpM = wid >> 2, warpN = wid & 3;   // 4 x 4 warp grid, 32x32 warp tiles
    const int bm = blockIdx.y * BM, bn = blockIdx.x * BN;
    const int nb = bn >> 7;
    const uint32_t sbase = (uint32_t)__cvta_generic_to_shared(smem);

    float accO[2][4][4];
    float accI[2][4][4];
    #pragma unroll
    for (int i = 0; i < 2; i++)
        #pragma unroll
        for (int j = 0; j < 4; j++)
            #pragma unroll
            for (int k = 0; k < 4; k++) { accO[i][j][k] = 0.0f; accI[i][j][k] = 0.0f; }

    auto load_stage = [&](int kt, int stage) {
        uint32_t sA = sbase + stage * STAGE_BYTES;
        uint32_t sB = sA + ABYTES;
        int k0 = kt * BK;
        #pragma unroll
        for (int i = 0; i < 2; i++) {
            int idx = t + i * NTHREADS;
            int row = idx >> 3, ci = idx & 7;
            cp_async16(sA + row * ARS + ci * 16,
                       g_xq + (size_t)(bm + row) * K_DIM + k0 + ci * 16);
            cp_async16(sB + row * ARS + ci * 16,
                       g_wq + (size_t)(bn + row) * K_DIM + k0 + ci * 16);
        }
    };

    const int NKT = K_DIM / BK;  // 16
    load_stage(0, 0);
    asm volatile("cp.async.commit_group;\n");
    load_stage(1, 1);
    asm volatile("cp.async.commit_group;\n");

    for (int kt = 0; kt < NKT; kt++) {
        int stage = kt % NSTAGE;
        asm volatile("cp.async.wait_group 1;\n");
        __syncthreads();
        if (kt + 2 < NKT) {
            load_stage(kt + 2, (kt + 2) % NSTAGE);
            asm volatile("cp.async.commit_group;\n");
        }
        uint32_t sA = sbase + stage * STAGE_BYTES;
        uint32_t sB = sA + ABYTES;
        #pragma unroll
        for (int s = 0; s < 4; s++) {        // four k32 steps per 128B tile
            uint32_t a[2][4];
            #pragma unroll
            for (int ma = 0; ma < 2; ma++) {
                int row = warpM * 32 + ma * 16 + (lane & 15);
                uint32_t addr = sA + row * ARS + (2 * s + (lane >> 4)) * 16;
                ldsm4(a[ma][0], a[ma][1], a[ma][2], a[ma][3], addr);
            }
            uint32_t b[2][4];
            #pragma unroll
            for (int g = 0; g < 2; g++) {
                int nrow = warpN * 32 + g * 16 + (((lane >> 4) & 1) << 3) + (lane & 7);
                int cch = 2 * s + ((lane >> 3) & 1);
                uint32_t addr = sB + nrow * ARS + cch * 16;
                ldsm4(b[g][0], b[g][1], b[g][2], b[g][3], addr);
            }
            #pragma unroll
            for (int ma = 0; ma < 2; ma++)
                #pragma unroll
                for (int na = 0; na < 4; na++)
                    qmma(accI[ma][na], a[ma][0], a[ma][1], a[ma][2], a[ma][3],
                         b[na >> 1][(na & 1) * 2 + 0], b[na >> 1][(na & 1) * 2 + 1]);
        }
        // end of chunk kt: fold scales exactly
        {
            float swc = g_sw[nb * KCH + kt];
            #pragma unroll
            for (int ma = 0; ma < 2; ma++) {
                int row0 = bm + warpM * 32 + ma * 16 + gid;
                float s0 = g_sx[row0 * KCH + kt] * swc;
                float s1 = g_sx[(row0 + 8) * KCH + kt] * swc;
                #pragma unroll
                for (int na = 0; na < 4; na++) {
                    accO[ma][na][0] += s0 * accI[ma][na][0];
                    accO[ma][na][1] += s0 * accI[ma][na][1];
                    accO[ma][na][2] += s1 * accI[ma][na][2];
                    accO[ma][na][3] += s1 * accI[ma][na][3];
                    accI[ma][na][0] = 0.0f; accI[ma][na][1] = 0.0f;
                    accI[ma][na][2] = 0.0f; accI[ma][na][3] = 0.0f;
                }
            }
        }
    }

    // epilogue: bf16-rounded values stored as FP32 (output buffer is float32)
    #pragma unroll
    for (int ma = 0; ma < 2; ma++) {
        int row0 = bm + warpM * 32 + ma * 16 + gid;
        #pragma unroll
        for (int na = 0; na < 4; na++) {
            int col = bn + warpN * 32 + na * 8 + tig * 2;
            float2 v0, v1;
            v0.x = bf16_round(accO[ma][na][0]);
            v0.y = bf16_round(accO[ma][na][1]);
            v1.x = bf16_round(accO[ma][na][2]);
            v1.y = bf16_round(accO[ma][na][3]);
            *reinterpret_cast<float2*>(out + (size_t)row0 * N_DIM + col) = v0;
            *reinterpret_cast<float2*>(out + (size_t)(row0 + 8) * N_DIM + col) = v1;
        }
    }
}

extern "C" void kernel_launch(void* const* d_in, const int* in_sizes, int n_in,
                              void* d_out, int out_size) {
    const float* x = (const float*)d_in[0];
    const float* w = (const float*)d_in[1];
    if (n_in >= 2 && in_sizes[0] == N_DIM * K_DIM && in_sizes[1] > in_sizes[0]) {
        x = (const float*)d_in[1];
        w = (const float*)d_in[0];
    }
    float* out = (float*)d_out;
    (void)out_size;

    static bool attr_set = false;
    if (!attr_set) {
        cudaFuncSetAttribute(gemm_kernel, cudaFuncAttributeMaxDynamicSharedMemorySize,
                             NSTAGE * STAGE_BYTES);
        attr_set = true;
    }

    quant_x_kernel<<<M_DIM * KCH / 8, 256>>>(x);
    quant_w_kernel<<<dim3(KCH, NBLK), 256>>>(w);
    gemm_kernel<<<dim3(N_DIM / BN, M_DIM / BM), NTHREADS, NSTAGE * STAGE_BYTES>>>(out);
}

// round 16
// speedup vs baseline: 1.1850x; 1.0704x over previous
#include <cuda_runtime.h>
#include <cuda_bf16.h>
#include <cuda_fp8.h>
#include <cstdint>

#define M_DIM 8192
#define N_DIM 2048
#define K_DIM 2048
#define KCH 16     // K / 128
#define NBLK 16    // N / 128

// ---------------- scratch (allocation-free: __device__ globals) ----------------
__device__ __align__(16) uint8_t g_xq[(size_t)M_DIM * K_DIM];  // 16 MB
__device__ __align__(16) uint8_t g_wq[(size_t)N_DIM * K_DIM];  //  4 MB
__device__ float g_sx[M_DIM * KCH];
__device__ float g_sw[NBLK * KCH];

// pack 4 floats -> 4 e4m3 bytes (RN, satfinite)
__device__ __forceinline__ uint32_t fp8x4(float a, float b, float c, float d, float r) {
    __nv_fp8x2_storage_t q01 =
        __nv_cvt_float2_to_fp8x2(make_float2(a * r, b * r), __NV_SATFINITE, __NV_E4M3);
    __nv_fp8x2_storage_t q23 =
        __nv_cvt_float2_to_fp8x2(make_float2(c * r, d * r), __NV_SATFINITE, __NV_E4M3);
    return (uint32_t)q01 | ((uint32_t)q23 << 16);
}

// ---------------- quantize x: per (row, 128-chunk) scale ----------------
__global__ void quant_x_kernel(const float* __restrict__ x) {
    int wid = threadIdx.x >> 5, lane = threadIdx.x & 31;
    int id = blockIdx.x * 8 + wid;
    int row = id >> 4, c = id & 15;
    const float4* src = reinterpret_cast<const float4*>(x + (size_t)row * K_DIM + c * 128);
    float4 v = src[lane];
    float amax = fmaxf(fmaxf(fabsf(v.x), fabsf(v.y)), fmaxf(fabsf(v.z), fabsf(v.w)));
    #pragma unroll
    for (int o = 16; o > 0; o >>= 1) amax = fmaxf(amax, __shfl_xor_sync(0xffffffffu, amax, o));
    amax = fmaxf(amax, 1e-4f);
    float r = 448.0f / amax;
    *reinterpret_cast<uint32_t*>(g_xq + (size_t)row * K_DIM + c * 128 + lane * 4) =
        fp8x4(v.x, v.y, v.z, v.w, r);
    if (lane == 0) g_sx[id] = amax / 448.0f;
}

// ---------------- quantize w: per 128x128 block scale ----------------
__global__ void quant_w_kernel(const float* __restrict__ w) {
    __shared__ float red[8];
    int nb = blockIdx.y, kc = blockIdx.x;
    int t = threadIdx.x;
    int lane = t & 31, wid = t >> 5;
    int rowInBlk = t >> 1;
    int colOff = (t & 1) * 64;
    const float4* base = reinterpret_cast<const float4*>(
        w + (size_t)(nb * 128 + rowInBlk) * K_DIM + kc * 128 + colOff);
    float4 v[16];
    float amax = 0.0f;
    #pragma unroll
    for (int i = 0; i < 16; i++) {
        v[i] = base[i];
        amax = fmaxf(amax, fmaxf(fmaxf(fabsf(v[i].x), fabsf(v[i].y)),
                                 fmaxf(fabsf(v[i].z), fabsf(v[i].w))));
    }
    #pragma unroll
    for (int o = 16; o > 0; o >>= 1) amax = fmaxf(amax, __shfl_xor_sync(0xffffffffu, amax, o));
    if (lane == 0) red[wid] = amax;
    __syncthreads();
    if (t == 0) {
        float m = red[0];
        #pragma unroll
        for (int i = 1; i < 8; i++) m = fmaxf(m, red[i]);
        red[0] = fmaxf(m, 1e-4f);
    }
    __syncthreads();
    float s = red[0];
    float r = 448.0f / s;
    uint8_t* dst = g_wq + (size_t)(nb * 128 + rowInBlk) * K_DIM + kc * 128 + colOff;
    #pragma unroll
    for (int i = 0; i < 16; i++)
        *reinterpret_cast<uint32_t*>(dst + i * 4) = fp8x4(v[i].x, v[i].y, v[i].z, v[i].w, r);
    if (t == 0) g_sw[nb * KCH + kc] = s / 448.0f;
}

// ---- GEMM: fp8 QMMA, BK=128, 512 threads, smem-cached scales, C!=D first qmma ----
#define BM 128
#define BN 128
#define BK 128
#define ARS 144                   // smem row stride bytes (128B data + 16 pad)
#define ABYTES (BM * ARS)         // 18432
#define BBYTES (BN * ARS)         // 18432
#define STAGE_BYTES (ABYTES + BBYTES)   // 36864
#define NSTAGE 3
#define NTHREADS 512
#define SMEM_SCALES (NSTAGE * STAGE_BYTES)          // sx cache: 128*16 floats
#define SMEM_SW (SMEM_SCALES + 128 * KCH * 4)       // sw cache: 16 floats
#define SMEM_TOT (SMEM_SW + KCH * 4)

__device__ __forceinline__ void cp_async16(uint32_t s, const void* g) {
    asm volatile("cp.async.cg.shared.global [%0], [%1], 16;\n" :: "r"(s), "l"(g));
}
__device__ __forceinline__ void ldsm4(uint32_t& r0, uint32_t& r1, uint32_t& r2, uint32_t& r3,
                                      uint32_t addr) {
    asm volatile("ldmatrix.sync.aligned.m8n8.x4.shared.b16 {%0,%1,%2,%3}, [%4];\n"
                 : "=r"(r0), "=r"(r1), "=r"(r2), "=r"(r3) : "r"(addr));
}
// accumulate form: D = A*B + D
__device__ __forceinline__ void qmma(float* c, uint32_t a0, uint32_t a1, uint32_t a2,
                                     uint32_t a3, uint32_t b0, uint32_t b1) {
    asm volatile(
        "mma.sync.aligned.m16n8k32.row.col.f32.e4m3.e4m3.f32 "
        "{%0,%1,%2,%3}, {%4,%5,%6,%7}, {%8,%9}, {%0,%1,%2,%3};\n"
        : "+f"(c[0]), "+f"(c[1]), "+f"(c[2]), "+f"(c[3])
        : "r"(a0), "r"(a1), "r"(a2), "r"(a3), "r"(b0), "r"(b1));
}
// init form: D = A*B + 0  (C is a zero operand distinct from D -> no accI zeroing, no WAR chain)
__device__ __forceinline__ void qmma0(float* d, uint32_t a0, uint32_t a1, uint32_t a2,
                                      uint32_t a3, uint32_t b0, uint32_t b1) {
    asm volatile(
        "mma.sync.aligned.m16n8k32.row.col.f32.e4m3.e4m3.f32 "
        "{%0,%1,%2,%3}, {%4,%5,%6,%7}, {%8,%9}, {%10,%10,%10,%10};\n"
        : "=f"(d[0]), "=f"(d[1]), "=f"(d[2]), "=f"(d[3])
        : "r"(a0), "r"(a1), "r"(a2), "r"(a3), "r"(b0), "r"(b1), "f"(0.0f));
}
__device__ __forceinline__ float bf16_round(float v) {
    return __bfloat162float(__float2bfloat16(v));
}

__global__ __launch_bounds__(NTHREADS, 1) void gemm_kernel(float* __restrict__ out) {
    extern __shared__ __align__(16) unsigned char smem[];
    const int t = threadIdx.x;
    const int lane = t & 31, wid = t >> 5;
    const int gid = lane >> 2;
    const int tig = lane & 3;
    const int warpM = wid >> 2, warpN = wid & 3;   // 4 x 4 warp grid, 32x32 warp tiles
    const int bm = blockIdx.y * BM, bn = blockIdx.x * BN;
    const int nb = bn >> 7;
    const uint32_t sbase = (uint32_t)__cvta_generic_to_shared(smem);
    float* sxs = reinterpret_cast<float*>(smem + SMEM_SCALES);  // [row][chunk] 128x16
    float* sws = reinterpret_cast<float*>(smem + SMEM_SW);      // [chunk] 16

    // one-time cooperative scale preload (coalesced: g_sx rows are contiguous in chunk)
    #pragma unroll
    for (int i = 0; i < (128 * KCH) / NTHREADS; i++) {
        int idx = t + i * NTHREADS;
        sxs[idx] = g_sx[(bm + (idx >> 4)) * KCH + (idx & 15)];
    }
    if (t < KCH) sws[t] = g_sw[nb * KCH + t];

    float accO[2][4][4];
    float accI[2][4][4];
    #pragma unroll
    for (int i = 0; i < 2; i++)
        #pragma unroll
        for (int j = 0; j < 4; j++)
            #pragma unroll
            for (int k = 0; k < 4; k++) accO[i][j][k] = 0.0f;

    auto load_stage = [&](int kt, int stage) {
        uint32_t sA = sbase + stage * STAGE_BYTES;
        uint32_t sB = sA + ABYTES;
        int k0 = kt * BK;
        #pragma unroll
        for (int i = 0; i < 2; i++) {
            int idx = t + i * NTHREADS;
            int row = idx >> 3, ci = idx & 7;
            cp_async16(sA + row * ARS + ci * 16,
                       g_xq + (size_t)(bm + row) * K_DIM + k0 + ci * 16);
            cp_async16(sB + row * ARS + ci * 16,
                       g_wq + (size_t)(bn + row) * K_DIM + k0 + ci * 16);
        }
    };

    const int NKT = K_DIM / BK;  // 16
    load_stage(0, 0);
    asm volatile("cp.async.commit_group;\n");
    load_stage(1, 1);
    asm volatile("cp.async.commit_group;\n");

    for (int kt = 0; kt < NKT; kt++) {
        int stage = kt % NSTAGE;
        asm volatile("cp.async.wait_group 1;\n");
        __syncthreads();
        if (kt + 2 < NKT) {
            load_stage(kt + 2, (kt + 2) % NSTAGE);
            asm volatile("cp.async.commit_group;\n");
        }
        uint32_t sA = sbase + stage * STAGE_BYTES;
        uint32_t sB = sA + ABYTES;
        #pragma unroll
        for (int s = 0; s < 4; s++) {
            uint32_t a[2][4];
            #pragma unroll
            for (int ma = 0; ma < 2; ma++) {
                int row = warpM * 32 + ma * 16 + (lane & 15);
                uint32_t addr = sA + row * ARS + (2 * s + (lane >> 4)) * 16;
                ldsm4(a[ma][0], a[ma][1], a[ma][2], a[ma][3], addr);
            }
            uint32_t b[2][4];
            #pragma unroll
            for (int g = 0; g < 2; g++) {
                int nrow = warpN * 32 + g * 16 + (((lane >> 4) & 1) << 3) + (lane & 7);
                int cch = 2 * s + ((lane >> 3) & 1);
                uint32_t addr = sB + nrow * ARS + cch * 16;
                ldsm4(b[g][0], b[g][1], b[g][2], b[g][3], addr);
            }
            #pragma unroll
            for (int ma = 0; ma < 2; ma++)
                #pragma unroll
                for (int na = 0; na < 4; na++) {
                    if (s == 0)
                        qmma0(accI[ma][na], a[ma][0], a[ma][1], a[ma][2], a[ma][3],
                              b[na >> 1][(na & 1) * 2 + 0], b[na >> 1][(na & 1) * 2 + 1]);
                    else
                        qmma(accI[ma][na], a[ma][0], a[ma][1], a[ma][2], a[ma][3],
                             b[na >> 1][(na & 1) * 2 + 0], b[na >> 1][(na & 1) * 2 + 1]);
                }
        }
        // end of chunk kt: fold scales exactly (scales from smem)
        {
            float swc = sws[kt];
            #pragma unroll
            for (int ma = 0; ma < 2; ma++) {
                int lrow = warpM * 32 + ma * 16 + gid;
                float s0 = sxs[lrow * KCH + kt] * swc;
                float s1 = sxs[(lrow + 8) * KCH + kt] * swc;
                #pragma unroll
                for (int na = 0; na < 4; na++) {
                    accO[ma][na][0] += s0 * accI[ma][na][0];
                    accO[ma][na][1] += s0 * accI[ma][na][1];
                    accO[ma][na][2] += s1 * accI[ma][na][2];
                    accO[ma][na][3] += s1 * accI[ma][na][3];
                }
            }
        }
    }

    // epilogue: bf16-rounded values stored as FP32 (output buffer is float32)
    #pragma unroll
    for (int ma = 0; ma < 2; ma++) {
        int row0 = bm + warpM * 32 + ma * 16 + gid;
        #pragma unroll
        for (int na = 0; na < 4; na++) {
            int col = bn + warpN * 32 + na * 8 + tig * 2;
            float2 v0, v1;
            v0.x = bf16_round(accO[ma][na][0]);
            v0.y = bf16_round(accO[ma][na][1]);
            v1.x = bf16_round(accO[ma][na][2]);
            v1.y = bf16_round(accO[ma][na][3]);
            *reinterpret_cast<float2*>(out + (size_t)row0 * N_DIM + col) = v0;
            *reinterpret_cast<float2*>(out + (size_t)(row0 + 8) * N_DIM + col) = v1;
        }
    }
}

extern "C" void kernel_launch(void* const* d_in, const int* in_sizes, int n_in,
                              void* d_out, int out_size) {
    const float* x = (const float*)d_in[0];
    const float* w = (const float*)d_in[1];
    if (n_in >= 2 && in_sizes[0] == N_DIM * K_DIM && in_sizes[1] > in_sizes[0]) {
        x = (const float*)d_in[1];
        w = (const float*)d_in[0];
    }
    float* out = (float*)d_out;
    (void)out_size;

    static bool attr_set = false;
    if (!attr_set) {
        cudaFuncSetAttribute(gemm_kernel, cudaFuncAttributeMaxDynamicSharedMemorySize,
                             SMEM_TOT);
        attr_set = true;
    }

    quant_x_kernel<<<M_DIM * KCH / 8, 256>>>(x);
    quant_w_kernel<<<dim3(KCH, NBLK), 256>>>(w);
    gemm_kernel<<<dim3(N_DIM / BN, M_DIM / BM), NTHREADS, SMEM_TOT>>>(out);
}